// round 17
// baseline (speedup 1.0000x reference)
#include <cuda_runtime.h>
#include <cuda_bf16.h>
#include <math.h>
#include <stdint.h>

// Problem constants
#define BB 64
#define TT 1024
#define QD 1024
#define CD 512
#define SPLITS 8
#define TCHUNK (TT / SPLITS)    // 128 rows per block
#define NT 256

#define CROWS  8                               // rows per pipeline chunk
#define NCHUNK (TCHUNK / CROWS)                // 16 chunks
#define CBYTES (CROWS * CD * 4)                // 16384 bytes
#define NSLOT  2

// Output layout (float32): context[B,CD] | a[B,T] | u_new[B] | sq_new[B]
#define CTX_OFF 0
#define A_OFF   (BB * CD)                 // 32768
#define U_OFF   (A_OFF + BB * TT)         // 98304
#define SQ_OFF  (U_OFF + BB)              // 98368

// Scratch
__device__ float        g_partial[BB * SPLITS * CD];
__device__ float        g_vsum[BB * SPLITS];
__device__ float        g_hdot[BB * SPLITS * 2];
__device__ unsigned int g_cnt[BB];          // zero-init; finalizer resets

__device__ __forceinline__ float alpha_v(
    const float* __restrict__ arow, int t, float ub, float sqb)
{
    const float cur  = arow[t];
    const float prev = (t > 0) ? arow[t - 1] : 0.0f;
    const float base = fmaf(-ub, cur, cur) + fmaf(ub, prev, 1e-6f);
    return __expf(sqb * __logf(base));   // base > 0 always
}

#define MBAR_INIT(mb) \
    asm volatile("mbarrier.init.shared.b64 [%0], 1;" :: "r"(mb) : "memory")

#define EXPECT_AND_COPY(mb, dst, src) do {                                        \
    asm volatile("mbarrier.arrive.expect_tx.shared.b64 _, [%0], %1;"              \
                 :: "r"(mb), "r"((unsigned)CBYTES) : "memory");                   \
    asm volatile("cp.async.bulk.shared::cta.global.mbarrier::complete_tx::bytes " \
                 "[%0], [%1], %2, [%3];"                                          \
                 :: "r"(dst), "l"(src), "r"((unsigned)CBYTES), "r"(mb)            \
                 : "memory");                                                     \
} while (0)

#define WAIT_PARITY(mb, ph) do {                                                  \
    unsigned _done = 0;                                                           \
    while (!_done) {                                                              \
        asm volatile("{\n\t.reg .pred p;\n\t"                                     \
            "mbarrier.try_wait.parity.acquire.cta.shared::cta.b64 p, [%1], %2, 0x989680;\n\t" \
            "selp.b32 %0, 1, 0, p;\n\t}"                                          \
            : "=r"(_done) : "r"(mb), "r"((unsigned)(ph)) : "memory");             \
    }                                                                             \
} while (0)

struct SM {
    alignas(128) float buf[NSLOT][CROWS * CD];  // 32 KB double buffer
    unsigned long long mbar[NSLOT];
    float  sa[TCHUNK];                          // v weights for slab
    float4 part[NT];                            // per-thread accumulators
    float  red[8], rs_[8];
    unsigned int tk;
};

// ---------------------------------------------------------------------------
// Single kernel, t-split + TMA double-buffer, prologue-overlapped.
// Grid (SPLITS, B), 256 threads. tid0 issues the first 2 TMA copies BEFORE
// the MUFU alpha phase (fetch overlaps prologue). Consumers: 4 LDS.128 +
// 16 FMA per thread per 16KB chunk (LDS floor 2cyc vs LDG 4cyc).
// Last-ticket block per batch finalizes ctx/a/heads.
// ---------------------------------------------------------------------------
__global__ void __launch_bounds__(NT) k_all(
    const float* __restrict__ inputs,
    const float* __restrict__ alpha,
    const float* __restrict__ u,
    const float* __restrict__ sq,
    const float* __restrict__ query,
    const float* __restrict__ W_u,  const float* __restrict__ b_u,
    const float* __restrict__ W_sq, const float* __restrict__ b_sq,
    float* __restrict__ out,
    float* __restrict__ partial,
    float* __restrict__ vsum,
    float* __restrict__ hdot,
    unsigned int* __restrict__ cnt)
{
    const int s   = blockIdx.x;
    const int b   = blockIdx.y;
    const int tid = threadIdx.x;
    const int lane = tid & 31;
    const int wid  = tid >> 5;

    __shared__ SM sm;

    const uint32_t mb0  = (uint32_t)__cvta_generic_to_shared(&sm.mbar[0]);
    const uint32_t mb1  = (uint32_t)__cvta_generic_to_shared(&sm.mbar[1]);
    const uint32_t bufu = (uint32_t)__cvta_generic_to_shared(&sm.buf[0][0]);
    const char* gsrc =
        (const char*)(inputs + ((size_t)b * TT + (size_t)s * TCHUNK) * CD);

    // --- tid0: init mbars + issue first 2 copies BEFORE the MUFU phase ---
    if (tid == 0) {
        MBAR_INIT(mb0); MBAR_INIT(mb1);
        asm volatile("fence.proxy.async.shared::cta;" ::: "memory");
        EXPECT_AND_COPY(mb0, bufu,          gsrc);
        EXPECT_AND_COPY(mb1, bufu + CBYTES, gsrc + CBYTES);
    }

    // --- alpha slab (threads 0..127, one v each); overlaps TMA fetch ---
    const float ub  = u[b];
    const float sqb = sq[b];
    const float* arow = alpha + (size_t)b * TT;
    if (tid < TCHUNK)
        sm.sa[tid] = alpha_v(arow, s * TCHUNK + tid, ub, sqb);
    __syncthreads();

    // chunk v-sum (warps 0..3 over sa[128])
    if (tid < TCHUNK) {
        float x = sm.sa[tid];
        #pragma unroll
        for (int o = 16; o > 0; o >>= 1) x += __shfl_xor_sync(0xffffffffu, x, o);
        if (lane == 0) sm.red[wid] = x;
    }
    __syncthreads();
    if (tid == 0)
        vsum[(size_t)b * SPLITS + s] =
            (sm.red[0] + sm.red[1]) + (sm.red[2] + sm.red[3]);

    // --- consume 16 chunks; thread owns group g, row-half 'half' ---
    const int g    = tid & 127;        // float4 column group (CD/4 = 128)
    const int half = tid >> 7;         // 0 or 1 -> rows 4*half..4*half+3
    float4 acc = {0,0,0,0};

    #pragma unroll
    for (int c = 0; c < NCHUNK; c++) {
        const uint32_t mb = (c & 1) ? mb1 : mb0;
        WAIT_PARITY(mb, (c >> 1) & 1);

        const float4* __restrict__ slot = (const float4*)&sm.buf[c & 1][0];
        const float*  __restrict__ w    = &sm.sa[c * CROWS + half * 4];
        const float4 v0 = slot[(size_t)(half * 4 + 0) * 128 + g];
        const float4 v1 = slot[(size_t)(half * 4 + 1) * 128 + g];
        const float4 v2 = slot[(size_t)(half * 4 + 2) * 128 + g];
        const float4 v3 = slot[(size_t)(half * 4 + 3) * 128 + g];
        const float w0 = w[0], w1 = w[1], w2 = w[2], w3 = w[3];
        acc.x = fmaf(w0, v0.x, acc.x); acc.y = fmaf(w0, v0.y, acc.y);
        acc.z = fmaf(w0, v0.z, acc.z); acc.w = fmaf(w0, v0.w, acc.w);
        acc.x = fmaf(w1, v1.x, acc.x); acc.y = fmaf(w1, v1.y, acc.y);
        acc.z = fmaf(w1, v1.z, acc.z); acc.w = fmaf(w1, v1.w, acc.w);
        acc.x = fmaf(w2, v2.x, acc.x); acc.y = fmaf(w2, v2.y, acc.y);
        acc.z = fmaf(w2, v2.z, acc.z); acc.w = fmaf(w2, v2.w, acc.w);
        acc.x = fmaf(w3, v3.x, acc.x); acc.y = fmaf(w3, v3.y, acc.y);
        acc.z = fmaf(w3, v3.z, acc.z); acc.w = fmaf(w3, v3.w, acc.w);

        __syncthreads();   // all threads done reading this slot
        if (tid == 0 && c + NSLOT < NCHUNK)
            EXPECT_AND_COPY(mb, bufu + (unsigned)(c & 1) * CBYTES,
                            gsrc + (size_t)(c + NSLOT) * CBYTES);
    }

    // combine the two half-accumulators per group
    sm.part[tid] = acc;
    __syncthreads();

    float4 r4;
    if (tid < 128) {
        const float4 p0 = sm.part[tid];
        const float4 p1 = sm.part[tid + 128];
        r4.x = p0.x + p1.x; r4.y = p0.y + p1.y;
        r4.z = p0.z + p1.z; r4.w = p0.w + p1.w;
        ((float4*)(partial + ((size_t)b * SPLITS + s) * CD))[tid] = r4;
    }

    // head-dot partials (threads 0..127)
    float hu = 0.0f, hs = 0.0f;
    if (tid < 128) {
        const float4 wu = ((const float4*)W_u)[tid];
        const float4 ws = ((const float4*)W_sq)[tid];
        hu = r4.x * wu.x + r4.y * wu.y + r4.z * wu.z + r4.w * wu.w;
        hs = r4.x * ws.x + r4.y * ws.y + r4.z * ws.z + r4.w * ws.w;
    }
    #pragma unroll
    for (int o = 16; o > 0; o >>= 1) {
        hu += __shfl_xor_sync(0xffffffffu, hu, o);
        hs += __shfl_xor_sync(0xffffffffu, hs, o);
    }
    if (tid < 128 && lane == 0) { sm.red[wid] = hu; sm.rs_[wid] = hs; }
    __syncthreads();

    if (tid == 0) {
        hdot[((size_t)b * SPLITS + s) * 2 + 0] =
            (sm.red[0] + sm.red[1]) + (sm.red[2] + sm.red[3]);
        hdot[((size_t)b * SPLITS + s) * 2 + 1] =
            (sm.rs_[0] + sm.rs_[1]) + (sm.rs_[2] + sm.rs_[3]);
        unsigned int old;
        asm volatile("atom.add.acq_rel.gpu.global.u32 %0, [%1], %2;"
                     : "=r"(old) : "l"(cnt + b), "r"(1u) : "memory");
        sm.tk = old;
    }
    __syncthreads();
    if (sm.tk != SPLITS - 1) return;

    // ===================== finalize batch b (last block) =====================
    if (tid == 0) cnt[b] = 0u;               // replay-safe reset

    float S = 0.0f;
    #pragma unroll
    for (int k = 0; k < SPLITS; k++) S += vsum[(size_t)b * SPLITS + k];
    const float inv = 1.0f / S;

    // normalized context: threads 0..127 reduce the 8 partials per group
    if (tid < 128) {
        const float4* __restrict__ p4 =
            (const float4*)(partial + (size_t)b * SPLITS * CD);
        float4 c4 = {0,0,0,0};
        #pragma unroll
        for (int k = 0; k < SPLITS; k++) {
            const float4 p = p4[(size_t)k * 128 + tid];
            c4.x += p.x; c4.y += p.y; c4.z += p.z; c4.w += p.w;
        }
        c4.x *= inv; c4.y *= inv; c4.z *= inv; c4.w *= inv;
        ((float4*)(out + CTX_OFF + (size_t)b * CD))[tid] = c4;
    }

    // normalized 'a' (recompute; alpha row L2-hot)
    #pragma unroll
    for (int t = tid; t < TT; t += NT)
        out[A_OFF + (size_t)b * TT + t] = alpha_v(arow, t, ub, sqb) * inv;

    // heads: query dot (QD/4 = 256 float4 = 1 per thread)
    const float4 q  = ((const float4*)(query + (size_t)b * QD))[tid];
    const float4 wq = ((const float4*)(W_u  + CD))[tid];
    const float4 wz = ((const float4*)(W_sq + CD))[tid];
    float pu = q.x * wq.x + q.y * wq.y + q.z * wq.z + q.w * wq.w;
    float ps = q.x * wz.x + q.y * wz.y + q.z * wz.z + q.w * wz.w;
    #pragma unroll
    for (int o = 16; o > 0; o >>= 1) {
        pu += __shfl_xor_sync(0xffffffffu, pu, o);
        ps += __shfl_xor_sync(0xffffffffu, ps, o);
    }
    __shared__ float fu[8], fs[8];
    if (lane == 0) { fu[wid] = pu; fs[wid] = ps; }
    __syncthreads();
    if (tid == 0) {
        float hu2 = 0.0f, hs2 = 0.0f;
        #pragma unroll
        for (int k = 0; k < SPLITS; k++) {
            hu2 += hdot[((size_t)b * SPLITS + k) * 2 + 0];
            hs2 += hdot[((size_t)b * SPLITS + k) * 2 + 1];
        }
        const float QU = ((fu[0] + fu[1]) + (fu[2] + fu[3]))
                       + ((fu[4] + fu[5]) + (fu[6] + fu[7]));
        const float QS = ((fs[0] + fs[1]) + (fs[2] + fs[3]))
                       + ((fs[4] + fs[5]) + (fs[6] + fs[7]));
        const float PU = hu2 * inv + QU + b_u[0];
        const float PS = hs2 * inv + QS + b_sq[0];
        out[U_OFF + b]  = 1.0f / (1.0f + expf(-PU));
        out[SQ_OFF + b] = 1.0f / (1.0f + expf(-PS)) + 1.0f;
    }
}

extern "C" void kernel_launch(void* const* d_in, const int* in_sizes, int n_in,
                              void* d_out, int out_size)
{
    const float* query  = (const float*)d_in[0];  // [B,1,QD]
    const float* inputs = (const float*)d_in[1];  // [B,T,CD]
    const float* alpha  = (const float*)d_in[2];  // [B,T]
    const float* u      = (const float*)d_in[3];  // [B,1]
    const float* sq     = (const float*)d_in[4];  // [B,1]
    const float* W_u    = (const float*)d_in[5];  // [QD+CD,1]
    const float* b_u    = (const float*)d_in[6];  // [1]
    const float* W_sq   = (const float*)d_in[7];  // [QD+CD,1]
    const float* b_sq   = (const float*)d_in[8];  // [1]
    float* out = (float*)d_out;

    float* partial; float* vsum; float* hdot; unsigned int* cnt;
    cudaGetSymbolAddress((void**)&partial, g_partial);
    cudaGetSymbolAddress((void**)&vsum, g_vsum);
    cudaGetSymbolAddress((void**)&hdot, g_hdot);
    cudaGetSymbolAddress((void**)&cnt, g_cnt);

    dim3 g(SPLITS, BB);
    k_all<<<g, NT>>>(inputs, alpha, u, sq, query,
                     W_u, b_u, W_sq, b_sq,
                     out, partial, vsum, hdot, cnt);
}